// round 2
// baseline (speedup 1.0000x reference)
#include <cuda_runtime.h>
#include <cuda_bf16.h>

// TripletLoss: loss = mean_t relu( ||a_t - p_t + eps||_2 - ||a_t - n_t + eps||_2 + margin )
// embeddings [N, 128] f32, triplet index arrays [T] int32. Output: 1 float.

#define MARGIN 0.5f
#define EPS 1e-6f
#define D 128
#define WARPS_PER_BLOCK 8
#define THREADS (WARPS_PER_BLOCK * 32)

__device__ float g_sum;

__global__ void init_kernel() {
    g_sum = 0.0f;
}

__global__ __launch_bounds__(THREADS) void triplet_kernel(
    const float* __restrict__ emb,
    const int* __restrict__ a_idx,
    const int* __restrict__ p_idx,
    const int* __restrict__ n_idx,
    int T)
{
    const int warp = (blockIdx.x * WARPS_PER_BLOCK) + (threadIdx.x >> 5);
    const int lane = threadIdx.x & 31;

    float local = 0.0f;

    if (warp < T) {
        const int ai = a_idx[warp];
        const int pi = p_idx[warp];
        const int ni = n_idx[warp];

        // Each lane loads one float4 (4 consecutive floats) from each row.
        const float4* arow = (const float4*)(emb + (size_t)ai * D);
        const float4* prow = (const float4*)(emb + (size_t)pi * D);
        const float4* nrow = (const float4*)(emb + (size_t)ni * D);

        float4 a4 = arow[lane];
        float4 p4 = prow[lane];
        float4 n4 = nrow[lane];

        float dp0 = a4.x - p4.x + EPS;
        float dp1 = a4.y - p4.y + EPS;
        float dp2 = a4.z - p4.z + EPS;
        float dp3 = a4.w - p4.w + EPS;
        float sp = dp0 * dp0 + dp1 * dp1 + dp2 * dp2 + dp3 * dp3;

        float dn0 = a4.x - n4.x + EPS;
        float dn1 = a4.y - n4.y + EPS;
        float dn2 = a4.z - n4.z + EPS;
        float dn3 = a4.w - n4.w + EPS;
        float sn = dn0 * dn0 + dn1 * dn1 + dn2 * dn2 + dn3 * dn3;

        // Warp butterfly reduction of both sums.
        #pragma unroll
        for (int off = 16; off > 0; off >>= 1) {
            sp += __shfl_xor_sync(0xFFFFFFFFu, sp, off);
            sn += __shfl_xor_sync(0xFFFFFFFFu, sn, off);
        }

        if (lane == 0) {
            float v = sqrtf(sp) - sqrtf(sn) + MARGIN;
            local = v > 0.0f ? v : 0.0f;
        }
    }

    // Block reduction: one partial per warp (lane 0 holds it).
    __shared__ float warp_part[WARPS_PER_BLOCK];
    if (lane == 0) warp_part[threadIdx.x >> 5] = local;
    __syncthreads();

    if (threadIdx.x == 0) {
        float s = 0.0f;
        #pragma unroll
        for (int w = 0; w < WARPS_PER_BLOCK; w++) s += warp_part[w];
        atomicAdd(&g_sum, s);
    }
}

__global__ void finalize_kernel(float* out, int T) {
    out[0] = g_sum / (float)T;
}

extern "C" void kernel_launch(void* const* d_in, const int* in_sizes, int n_in,
                              void* d_out, int out_size) {
    const float* emb   = (const float*)d_in[0];
    // d_in[1] = labels (unused; triplets already mined)
    const int* a_idx   = (const int*)d_in[2];
    const int* p_idx   = (const int*)d_in[3];
    const int* n_idx   = (const int*)d_in[4];
    float* out         = (float*)d_out;
    const int T        = in_sizes[2];

    init_kernel<<<1, 1>>>();

    int blocks = (T + WARPS_PER_BLOCK - 1) / WARPS_PER_BLOCK;
    triplet_kernel<<<blocks, THREADS>>>(emb, a_idx, p_idx, n_idx, T);

    finalize_kernel<<<1, 1>>>(out, T);
}